// round 8
// baseline (speedup 1.0000x reference)
#include <cuda_runtime.h>
#include <cuda_fp16.h>
#include <cstdint>

#define N_NODES    2048
#define FDIM       256
#define HID        64
#define TEMPLATE_N 10
#define TRIG_ELEMS (N_NODES * FDIM)
#define EW1B_OFF   (FDIM * HID)

// device scratch
__device__ float g_h3[FDIM];
__device__ float g_base[HID];            // h3@(w1a+w1b) + eb1
__device__ float g_npa[N_NODES * HID];   // 0.1*noise@w1a (rows 0..9 zero)
__device__ float g_npb[N_NODES * HID];   // 0.1*noise@w1b (rows 0..9 zero)

// ---- f32x2 helpers (prep GEMM only) --------------------------------------
__device__ __forceinline__ unsigned long long f2_fma(unsigned long long a, unsigned long long b, unsigned long long c) {
    unsigned long long r; asm("fma.rn.f32x2 %0, %1, %2, %3;" : "=l"(r) : "l"(a), "l"(b), "l"(c)); return r;
}
__device__ __forceinline__ void f2_unpack(float& lo, float& hi, unsigned long long v) {
    asm("mov.b64 {%0, %1}, %2;" : "=f"(lo), "=f"(hi) : "l"(v));
}
__device__ __forceinline__ unsigned long long f2_pack(float lo, float hi) {
    unsigned long long r; asm("mov.b64 %0, {%1, %2};" : "=l"(r) : "f"(lo), "f"(hi)); return r;
}

// ---------------------------------------------------------------------------
// Kernel P: 257 blocks x 256 threads.
//   block 0   : MLP -> g_h3, g_base
//   blocks 1+ : noise GEMM, 8 rows/block (c = tid&127 col, rh = tid>>7 rows)
// ---------------------------------------------------------------------------
#define KP_ROWS   8
#define NS_STRIDE 12   // 8 + pad; k*12 floats -> 16B aligned

__global__ void __launch_bounds__(256, 2)
kP_prep(const float* __restrict__ cf, const int* __restrict__ sel,
        const float* __restrict__ w1, const float* __restrict__ b1,
        const float* __restrict__ w2, const float* __restrict__ b2,
        const float* __restrict__ w3, const float* __restrict__ b3,
        const float* __restrict__ ew1, const float* __restrict__ eb1,
        const float* __restrict__ noise)
{
    __shared__ float sBuf[FDIM * NS_STRIDE];   // 12 KB
    const int tid = threadIdx.x;

    if (blockIdx.x == 0) {
        float* proto = sBuf;
        float* h1    = sBuf + 256;
        float* h2    = sBuf + 320;
        float* h3S   = sBuf + 384;
        float* part  = sBuf + 640;

        {
            float s = 0.f;
            #pragma unroll
            for (int r = 0; r < TEMPLATE_N; ++r)
                s += cf[(size_t)sel[r] * FDIM + tid];
            proto[tid] = s * (1.0f / TEMPLATE_N);
        }
        __syncthreads();

        {
            const int c = tid & 63, q = tid >> 6, k0 = q * 64;
            float acc = 0.f;
            #pragma unroll 8
            for (int k = 0; k < 64; ++k)
                acc = fmaf(proto[k0 + k], w1[(k0 + k) * HID + c], acc);
            part[tid] = acc;
        }
        __syncthreads();
        if (tid < HID)
            h1[tid] = fmaxf(part[tid] + part[64 + tid] + part[128 + tid] + part[192 + tid] + b1[tid], 0.f);
        __syncthreads();

        {
            const int c = tid & 63, q = tid >> 6, k0 = q * 16;
            float acc = 0.f;
            #pragma unroll
            for (int k = 0; k < 16; ++k)
                acc = fmaf(h1[k0 + k], w2[(k0 + k) * HID + c], acc);
            part[tid] = acc;
        }
        __syncthreads();
        if (tid < HID)
            h2[tid] = fmaxf(part[tid] + part[64 + tid] + part[128 + tid] + part[192 + tid] + b2[tid], 0.f);
        __syncthreads();

        {
            float acc = b3[tid];
            #pragma unroll 8
            for (int k = 0; k < HID; ++k)
                acc = fmaf(h2[k], w3[k * FDIM + tid], acc);
            float v = __fdividef(1.0f, 1.0f + __expf(-acc));
            g_h3[tid] = v;
            h3S[tid]  = v;
        }
        __syncthreads();

        {
            const int c = tid & 63, q = tid >> 6, k0 = q * 64;
            float acc = 0.f;
            #pragma unroll 4
            for (int k = 0; k < 64; ++k) {
                float w = ew1[(k0 + k) * HID + c] + ew1[EW1B_OFF + (k0 + k) * HID + c];
                acc = fmaf(h3S[k0 + k], w, acc);
            }
            part[tid] = acc;
        }
        __syncthreads();
        if (tid < HID)
            g_base[tid] = part[tid] + part[64 + tid] + part[128 + tid] + part[192 + tid] + eb1[tid];
        return;
    }

    // ---------------- noise GEMM (blocks 1..256), 8 rows each ----------------
    float* nS = sBuf;
    const int r0 = (blockIdx.x - 1) * KP_ROWS;

    #pragma unroll
    for (int u = 0; u < KP_ROWS; ++u) {
        const int r = r0 + u;
        float v = 0.f;
        if (r >= TEMPLATE_N)
            v = 0.1f * noise[(size_t)(r - TEMPLATE_N) * FDIM + tid];
        nS[tid * NS_STRIDE + u] = v;
    }
    __syncthreads();

    const int c  = tid & 127;
    const int rh = tid >> 7;
    const bool is_pa = (c < HID);
    const float* wcol = ew1 + (is_pa ? c : (EW1B_OFF + (c - HID)));

    unsigned long long acc0 = f2_pack(0.f, 0.f), acc1 = acc0;

    #pragma unroll 8
    for (int k = 0; k < FDIM; ++k) {
        const float w = wcol[k * HID];
        const unsigned long long wp = f2_pack(w, w);
        const ulonglong2 A = *reinterpret_cast<const ulonglong2*>(nS + k * NS_STRIDE + rh * 4);
        acc0 = f2_fma(A.x, wp, acc0);
        acc1 = f2_fma(A.y, wp, acc1);
    }

    float* dst = (is_pa ? g_npa : g_npb);
    const int cc = is_pa ? c : (c - HID);
    const int rb = r0 + rh * 4;
    float lo, hi;
    f2_unpack(lo, hi, acc0);
    dst[rb * HID + cc]       = lo;
    dst[(rb + 1) * HID + cc] = hi;
    f2_unpack(lo, hi, acc1);
    dst[(rb + 2) * HID + cc] = lo;
    dst[(rb + 3) * HID + cc] = hi;
}

// ---------------------------------------------------------------------------
// Kernel E: 576 tiles (256 j x 16 i), 256 threads, 4 CTAs/SM -> ONE wave.
//   w2 in shared (uniform broadcast), pb per-thread regs.
// ---------------------------------------------------------------------------
#define TI 16
#define TJ 256
#define N_TILES 576     // sum over jt of (16*jt + 16)

__global__ void __launch_bounds__(TJ, 4)
kE_edges(const float* __restrict__ noise,
         const float* __restrict__ ew2,
         const float* __restrict__ eb2,
         float* __restrict__ out_trig,
         float* __restrict__ out_edge)
{
    __shared__ __half2 paS[TI * 32];          // 512 half2 = 2 KB
    __shared__ __half2 w2S[32];               // 128 B
    const int tid = threadIdx.x;

    // ---- stage 0: trig rows (<=4 per block) ----
    {
        const float h3v = g_h3[tid];
        for (int r = blockIdx.x; r < N_NODES; r += N_TILES) {
            float v = h3v;
            if (r >= TEMPLATE_N)
                v = fmaf(0.1f, noise[(size_t)(r - TEMPLATE_N) * FDIM + tid], v);
            out_trig[(size_t)r * FDIM + tid] = v;
        }
    }

    // ---- tile mapping: jt has 16*jt+16 i-tiles ----
    int rem = blockIdx.x, jt;
    for (jt = 0; jt < 8; ++jt) { const int n = 16 * jt + 16; if (rem < n) break; rem -= n; }
    const int it = rem;
    const int j0 = jt * TJ;
    const int i0 = it * TI;

    // ---- stage 1a: pa tile -> fp16 smem (512 entries, 2 per thread) ----
    #pragma unroll
    for (int idx = tid; idx < TI * 32; idx += TJ) {
        const int ii = idx >> 5, kp = idx & 31;
        const float lo = g_npa[(i0 + ii) * HID + 2 * kp]     + g_base[2 * kp];
        const float hi = g_npa[(i0 + ii) * HID + 2 * kp + 1] + g_base[2 * kp + 1];
        paS[idx] = __floats2half2_rn(lo, hi);
    }
    if (tid < 16) {
        const float4 w = __ldg(reinterpret_cast<const float4*>(ew2) + tid);
        w2S[2 * tid]     = __floats2half2_rn(w.x, w.y);
        w2S[2 * tid + 1] = __floats2half2_rn(w.z, w.w);
    }

    // ---- stage 1b: pb row -> fp16 regs ----
    const int j = j0 + tid;
    __half2 pb2[32];
    {
        const float4* pbp = reinterpret_cast<const float4*>(g_npb + j * HID);
        #pragma unroll
        for (int q = 0; q < 16; ++q) {
            float4 v = pbp[q];
            pb2[2 * q]     = __floats2half2_rn(v.x, v.y);
            pb2[2 * q + 1] = __floats2half2_rn(v.z, v.w);
        }
    }
    const float ebb = eb2[0];
    const __half2 one2 = __floats2half2_rn(1.0f, 1.0f);
    __syncthreads();

    // ---- stage 2: pair loop, 2 i's per iteration, 8 acc chains ----
    const uint4* paS4 = reinterpret_cast<const uint4*>(paS);
    const uint4* w2S4 = reinterpret_cast<const uint4*>(w2S);

    #pragma unroll
    for (int ii = 0; ii < TI; ii += 2) {
        __half2 a0 = __float2half2_rn(0.f), a1 = a0, a2 = a0, a3 = a0;
        __half2 b0 = a0, b1 = a0, b2v = a0, b3v = a0;

        #pragma unroll
        for (int q = 0; q < 8; ++q) {
            const uint4 PA = paS4[ii * 8 + q];
            const uint4 PB = paS4[(ii + 1) * 8 + q];
            const uint4 W  = w2S4[q];                      // uniform broadcast
            const __half2 w0  = *reinterpret_cast<const __half2*>(&W.x);
            const __half2 w1v = *reinterpret_cast<const __half2*>(&W.y);
            const __half2 w2v = *reinterpret_cast<const __half2*>(&W.z);
            const __half2 w3v = *reinterpret_cast<const __half2*>(&W.w);
            const int kp = q * 4;
            __half2 h;
            h = __hfma2_relu(*reinterpret_cast<const __half2*>(&PA.x), one2, pb2[kp + 0]); a0 = __hfma2(h, w0, a0);
            h = __hfma2_relu(*reinterpret_cast<const __half2*>(&PA.y), one2, pb2[kp + 1]); a1 = __hfma2(h, w1v, a1);
            h = __hfma2_relu(*reinterpret_cast<const __half2*>(&PA.z), one2, pb2[kp + 2]); a2 = __hfma2(h, w2v, a2);
            h = __hfma2_relu(*reinterpret_cast<const __half2*>(&PA.w), one2, pb2[kp + 3]); a3 = __hfma2(h, w3v, a3);
            h = __hfma2_relu(*reinterpret_cast<const __half2*>(&PB.x), one2, pb2[kp + 0]); b0  = __hfma2(h, w0, b0);
            h = __hfma2_relu(*reinterpret_cast<const __half2*>(&PB.y), one2, pb2[kp + 1]); b1  = __hfma2(h, w1v, b1);
            h = __hfma2_relu(*reinterpret_cast<const __half2*>(&PB.z), one2, pb2[kp + 2]); b2v = __hfma2(h, w2v, b2v);
            h = __hfma2_relu(*reinterpret_cast<const __half2*>(&PB.w), one2, pb2[kp + 3]); b3v = __hfma2(h, w3v, b3v);
        }

        {
            const int i = i0 + ii;
            if (j > i) {
                const __half2 st = __hadd2(__hadd2(a0, a1), __hadd2(a2, a3));
                const float2 f = __half22float2(st);
                const float s = f.x + f.y + ebb;
                const float pr = __fdividef(1.0f, 1.0f + __expf(-s));
                const int base = i * (2 * N_NODES - i - 1) / 2;
                out_edge[base + (j - i - 1)] = pr;
            }
        }
        {
            const int i = i0 + ii + 1;
            if (j > i) {
                const __half2 st = __hadd2(__hadd2(b0, b1), __hadd2(b2v, b3v));
                const float2 f = __half22float2(st);
                const float s = f.x + f.y + ebb;
                const float pr = __fdividef(1.0f, 1.0f + __expf(-s));
                const int base = i * (2 * N_NODES - i - 1) / 2;
                out_edge[base + (j - i - 1)] = pr;
            }
        }
    }
}

// ---------------------------------------------------------------------------
extern "C" void kernel_launch(void* const* d_in, const int* in_sizes, int n_in,
                              void* d_out, int out_size)
{
    const float* cf    = (const float*)d_in[0];
    const int*   sel   = (const int*)  d_in[1];
    const float* noise = (const float*)d_in[2];
    const float* g1w   = (const float*)d_in[3];
    const float* g1b   = (const float*)d_in[4];
    const float* g2w   = (const float*)d_in[5];
    const float* g2b   = (const float*)d_in[6];
    const float* g3w   = (const float*)d_in[7];
    const float* g3b   = (const float*)d_in[8];
    const float* ew1   = (const float*)d_in[9];
    const float* eb1   = (const float*)d_in[10];
    const float* ew2   = (const float*)d_in[11];
    const float* eb2   = (const float*)d_in[12];

    float* out      = (float*)d_out;
    float* out_trig = out;
    float* out_edge = out + TRIG_ELEMS;

    kP_prep<<<257, 256>>>(cf, sel, g1w, g1b, g2w, g2b, g3w, g3b, ew1, eb1, noise);
    kE_edges<<<N_TILES, TJ>>>(noise, ew2, eb2, out_trig, out_edge);
}

// round 9
// speedup vs baseline: 1.3915x; 1.3915x over previous
#include <cuda_runtime.h>
#include <cuda_fp16.h>
#include <cstdint>

#define N_NODES    2048
#define FDIM       256
#define HID        64
#define TEMPLATE_N 10
#define TRIG_ELEMS (N_NODES * FDIM)
#define EW1B_OFF   (FDIM * HID)

// device scratch (fp16 operand caches, produced by kP)
__device__ float   g_h3[FDIM];
__device__ __half2 g_baseh2[HID / 2];          // base = h3@(w1a+w1b)+eb1
__device__ __half2 g_npah2[N_NODES * HID / 2]; // 0.1*noise@w1a  (rows<10: 0)
__device__ __half2 g_npbh2[N_NODES * HID / 2]; // 0.1*noise@w1b  (rows<10: 0)

// ---- f32x2 helpers (prep GEMM only) --------------------------------------
__device__ __forceinline__ unsigned long long f2_fma(unsigned long long a, unsigned long long b, unsigned long long c) {
    unsigned long long r; asm("fma.rn.f32x2 %0, %1, %2, %3;" : "=l"(r) : "l"(a), "l"(b), "l"(c)); return r;
}
__device__ __forceinline__ void f2_unpack(float& lo, float& hi, unsigned long long v) {
    asm("mov.b64 {%0, %1}, %2;" : "=f"(lo), "=f"(hi) : "l"(v));
}
__device__ __forceinline__ unsigned long long f2_pack(float lo, float hi) {
    unsigned long long r; asm("mov.b64 %0, {%1, %2};" : "=l"(r) : "f"(lo), "f"(hi)); return r;
}

// ---------------------------------------------------------------------------
// Kernel P: 257 blocks x 256 threads.
//   block 0   : MLP -> g_h3, g_baseh2
//   blocks 1+ : noise GEMM, 8 rows/block -> g_npah2 / g_npbh2 (fp16)
// ---------------------------------------------------------------------------
#define KP_ROWS   8
#define NS_STRIDE 12   // 8 + pad; k*12 floats -> 16B aligned

__global__ void __launch_bounds__(256, 2)
kP_prep(const float* __restrict__ cf, const int* __restrict__ sel,
        const float* __restrict__ w1, const float* __restrict__ b1,
        const float* __restrict__ w2, const float* __restrict__ b2,
        const float* __restrict__ w3, const float* __restrict__ b3,
        const float* __restrict__ ew1, const float* __restrict__ eb1,
        const float* __restrict__ noise)
{
    __shared__ float sBuf[FDIM * NS_STRIDE];   // 12 KB
    const int tid = threadIdx.x;

    if (blockIdx.x == 0) {
        float* proto = sBuf;
        float* h1    = sBuf + 256;
        float* h2    = sBuf + 320;
        float* h3S   = sBuf + 384;
        float* part  = sBuf + 640;

        {
            float s = 0.f;
            #pragma unroll
            for (int r = 0; r < TEMPLATE_N; ++r)
                s += cf[(size_t)sel[r] * FDIM + tid];
            proto[tid] = s * (1.0f / TEMPLATE_N);
        }
        __syncthreads();

        {
            const int c = tid & 63, q = tid >> 6, k0 = q * 64;
            float acc = 0.f;
            #pragma unroll 16
            for (int k = 0; k < 64; ++k)
                acc = fmaf(proto[k0 + k], w1[(k0 + k) * HID + c], acc);
            part[tid] = acc;
        }
        __syncthreads();
        if (tid < HID)
            h1[tid] = fmaxf(part[tid] + part[64 + tid] + part[128 + tid] + part[192 + tid] + b1[tid], 0.f);
        __syncthreads();

        {
            const int c = tid & 63, q = tid >> 6, k0 = q * 16;
            float acc = 0.f;
            #pragma unroll
            for (int k = 0; k < 16; ++k)
                acc = fmaf(h1[k0 + k], w2[(k0 + k) * HID + c], acc);
            part[tid] = acc;
        }
        __syncthreads();
        if (tid < HID)
            h2[tid] = fmaxf(part[tid] + part[64 + tid] + part[128 + tid] + part[192 + tid] + b2[tid], 0.f);
        __syncthreads();

        {
            float acc = b3[tid];
            #pragma unroll 16
            for (int k = 0; k < HID; ++k)
                acc = fmaf(h2[k], w3[k * FDIM + tid], acc);
            float v = __fdividef(1.0f, 1.0f + __expf(-acc));
            g_h3[tid] = v;
            h3S[tid]  = v;
        }
        __syncthreads();

        {
            const int c = tid & 63, q = tid >> 6, k0 = q * 64;
            float acc = 0.f;
            #pragma unroll 8
            for (int k = 0; k < 64; ++k) {
                float w = ew1[(k0 + k) * HID + c] + ew1[EW1B_OFF + (k0 + k) * HID + c];
                acc = fmaf(h3S[k0 + k], w, acc);
            }
            part[tid] = acc;
        }
        __syncthreads();
        if (tid < HID) {
            float v = part[tid] + part[64 + tid] + part[128 + tid] + part[192 + tid] + eb1[tid];
            reinterpret_cast<__half*>(g_baseh2)[tid] = __float2half(v);
        }
        return;
    }

    // ---------------- noise GEMM (blocks 1..256), 8 rows each ----------------
    float* nS = sBuf;
    const int r0 = (blockIdx.x - 1) * KP_ROWS;

    #pragma unroll
    for (int u = 0; u < KP_ROWS; ++u) {
        const int r = r0 + u;
        float v = 0.f;
        if (r >= TEMPLATE_N)
            v = 0.1f * noise[(size_t)(r - TEMPLATE_N) * FDIM + tid];
        nS[tid * NS_STRIDE + u] = v;
    }
    __syncthreads();

    const int c  = tid & 127;
    const int rh = tid >> 7;
    const bool is_pa = (c < HID);
    const float* wcol = ew1 + (is_pa ? c : (EW1B_OFF + (c - HID)));

    unsigned long long acc0 = f2_pack(0.f, 0.f), acc1 = acc0;

    #pragma unroll 8
    for (int k = 0; k < FDIM; ++k) {
        const float w = wcol[k * HID];
        const unsigned long long wp = f2_pack(w, w);
        const ulonglong2 A = *reinterpret_cast<const ulonglong2*>(nS + k * NS_STRIDE + rh * 4);
        acc0 = f2_fma(A.x, wp, acc0);
        acc1 = f2_fma(A.y, wp, acc1);
    }

    __half* dst = reinterpret_cast<__half*>(is_pa ? g_npah2 : g_npbh2);
    const int cc = is_pa ? c : (c - HID);
    const int rb = r0 + rh * 4;
    float lo, hi;
    f2_unpack(lo, hi, acc0);
    dst[(rb + 0) * HID + cc] = __float2half(lo);
    dst[(rb + 1) * HID + cc] = __float2half(hi);
    f2_unpack(lo, hi, acc1);
    dst[(rb + 2) * HID + cc] = __float2half(lo);
    dst[(rb + 3) * HID + cc] = __float2half(hi);
}

// ---------------------------------------------------------------------------
// Kernel E: 544 tiles (128 j x 32 i), 256 threads, 4 CTAs/SM, ONE wave.
//   Thread = (jl = tid&127, kh = tid>>7): owns column j, k-half kh (32 k's).
//   pb half (4 uint4 regs), w2 half (4 uint4 regs), pa tile in fp16 smem.
//   Partial dots meet in sumS; one sync; fused epilogue.
// ---------------------------------------------------------------------------
#define TI 32
#define TJ 128
#define N_TILES 544     // sum over jt=0..15 of (4*jt + 4)

__global__ void __launch_bounds__(256, 4)
kE_edges(const float* __restrict__ noise,
         const float* __restrict__ ew2,
         const float* __restrict__ eb2,
         float* __restrict__ out_trig,
         float* __restrict__ out_edge)
{
    __shared__ __half2 paS[TI * 32];          // 4 KB   [ii][kp], kp = k/2
    __shared__ float   sumS[2 * TI * TJ];     // 32 KB  [(kh*TI+ii)*TJ + jl]
    __shared__ __half2 w2S[32];               // 128 B
    const int tid = threadIdx.x;

    // ---- stage 0: trig rows (<=4 per block) ----
    {
        const float h3v = g_h3[tid];
        for (int r = blockIdx.x; r < N_NODES; r += N_TILES) {
            float v = h3v;
            if (r >= TEMPLATE_N)
                v = fmaf(0.1f, noise[(size_t)(r - TEMPLATE_N) * FDIM + tid], v);
            out_trig[(size_t)r * FDIM + tid] = v;
        }
    }

    // ---- tile mapping: jt has 4*jt+4 i-tiles ----
    int rem = blockIdx.x, jt;
    for (jt = 0; jt < 16; ++jt) { const int n = 4 * jt + 4; if (rem < n) break; rem -= n; }
    const int it = rem;
    const int j0 = jt * TJ;
    const int i0 = it * TI;

    const int jl = tid & 127;
    const int kh = tid >> 7;

    // ---- pa tile: half2 loads + half2 base add, 4 entries per thread ----
    #pragma unroll
    for (int idx = tid; idx < TI * 32; idx += 256) {
        const int ii = idx >> 5, kp = idx & 31;
        paS[idx] = __hadd2(g_npah2[(i0 + ii) * 32 + kp], g_baseh2[kp]);
    }
    if (tid < 16) {
        const float4 w = __ldg(reinterpret_cast<const float4*>(ew2) + tid);
        w2S[2 * tid]     = __floats2half2_rn(w.x, w.y);
        w2S[2 * tid + 1] = __floats2half2_rn(w.z, w.w);
    }

    // ---- pb: this thread's k-half of row j (4 x uint4 = 32 halves) ----
    uint4 pbr[4];
    {
        const uint4* pbp = reinterpret_cast<const uint4*>(g_npbh2 + (j0 + jl) * 32 + kh * 16);
        #pragma unroll
        for (int q = 0; q < 4; ++q) pbr[q] = pbp[q];
    }
    __syncthreads();

    // ---- w2 k-half into regs ----
    uint4 w2r[4];
    {
        const uint4* wp = reinterpret_cast<const uint4*>(w2S) + kh * 4;
        #pragma unroll
        for (int q = 0; q < 4; ++q) w2r[q] = wp[q];
    }

    // ---- pair loop: 2 i's per iteration, 8 acc chains ----
    const uint4* paS4 = reinterpret_cast<const uint4*>(paS);   // 8 uint4 per i-row
    #pragma unroll 2
    for (int ii = 0; ii < TI; ii += 2) {
        __half2 a0 = __float2half2_rn(0.f), a1 = a0, a2 = a0, a3 = a0;
        __half2 b0 = a0, b1 = a0, b2 = a0, b3 = a0;

        const uint4* pa0 = paS4 + ii * 8 + kh * 4;
        const uint4* pa1 = pa0 + 8;

        #pragma unroll
        for (int q = 0; q < 4; ++q) {
            const uint4 PA = pa0[q];               // uniform LDS.128 broadcast
            const uint4 PB = pa1[q];
            const uint4 W  = w2r[q];
            const __half2 w0 = *reinterpret_cast<const __half2*>(&W.x);
            const __half2 w1v = *reinterpret_cast<const __half2*>(&W.y);
            const __half2 w2v = *reinterpret_cast<const __half2*>(&W.z);
            const __half2 w3v = *reinterpret_cast<const __half2*>(&W.w);
            const uint4 B = pbr[q];
            const __half2 q0 = *reinterpret_cast<const __half2*>(&B.x);
            const __half2 q1 = *reinterpret_cast<const __half2*>(&B.y);
            const __half2 q2 = *reinterpret_cast<const __half2*>(&B.z);
            const __half2 q3 = *reinterpret_cast<const __half2*>(&B.w);
            const __half2 one2 = __half2half2(__ushort_as_half(0x3C00));
            __half2 h;
            h = __hfma2_relu(*reinterpret_cast<const __half2*>(&PA.x), one2, q0); a0 = __hfma2(h, w0, a0);
            h = __hfma2_relu(*reinterpret_cast<const __half2*>(&PA.y), one2, q1); a1 = __hfma2(h, w1v, a1);
            h = __hfma2_relu(*reinterpret_cast<const __half2*>(&PA.z), one2, q2); a2 = __hfma2(h, w2v, a2);
            h = __hfma2_relu(*reinterpret_cast<const __half2*>(&PA.w), one2, q3); a3 = __hfma2(h, w3v, a3);
            h = __hfma2_relu(*reinterpret_cast<const __half2*>(&PB.x), one2, q0); b0 = __hfma2(h, w0, b0);
            h = __hfma2_relu(*reinterpret_cast<const __half2*>(&PB.y), one2, q1); b1 = __hfma2(h, w1v, b1);
            h = __hfma2_relu(*reinterpret_cast<const __half2*>(&PB.z), one2, q2); b2 = __hfma2(h, w2v, b2);
            h = __hfma2_relu(*reinterpret_cast<const __half2*>(&PB.w), one2, q3); b3 = __hfma2(h, w3v, b3);
        }

        {
            const __half2 t = __hadd2(__hadd2(a0, a1), __hadd2(a2, a3));
            const float2 f = __half22float2(t);
            sumS[(kh * TI + ii) * TJ + jl] = f.x + f.y;
        }
        {
            const __half2 t = __hadd2(__hadd2(b0, b1), __hadd2(b2, b3));
            const float2 f = __half22float2(t);
            sumS[(kh * TI + ii + 1) * TJ + jl] = f.x + f.y;
        }
    }
    __syncthreads();

    // ---- epilogue: combine halves, sigmoid, store (coalesced in j) ----
    const float ebb = eb2[0];
    #pragma unroll
    for (int u = 0; u < 16; ++u) {
        const int idx = tid + u * 256;
        const int il  = idx >> 7;
        const int jl2 = idx & 127;
        const int i = i0 + il;
        const int jj = j0 + jl2;
        if (jj > i) {
            const float s = sumS[il * TJ + jl2] + sumS[(TI + il) * TJ + jl2] + ebb;
            const float pr = __fdividef(1.0f, 1.0f + __expf(-s));
            const int base = i * (2 * N_NODES - i - 1) / 2;
            out_edge[base + (jj - i - 1)] = pr;
        }
    }
}

// ---------------------------------------------------------------------------
extern "C" void kernel_launch(void* const* d_in, const int* in_sizes, int n_in,
                              void* d_out, int out_size)
{
    const float* cf    = (const float*)d_in[0];
    const int*   sel   = (const int*)  d_in[1];
    const float* noise = (const float*)d_in[2];
    const float* g1w   = (const float*)d_in[3];
    const float* g1b   = (const float*)d_in[4];
    const float* g2w   = (const float*)d_in[5];
    const float* g2b   = (const float*)d_in[6];
    const float* g3w   = (const float*)d_in[7];
    const float* g3b   = (const float*)d_in[8];
    const float* ew1   = (const float*)d_in[9];
    const float* eb1   = (const float*)d_in[10];
    const float* ew2   = (const float*)d_in[11];
    const float* eb2   = (const float*)d_in[12];

    float* out      = (float*)d_out;
    float* out_trig = out;
    float* out_edge = out + TRIG_ELEMS;

    kP_prep<<<257, 256>>>(cf, sel, g1w, g1b, g2w, g2b, g3w, g3b, ew1, eb1, noise);
    kE_edges<<<N_TILES, TJ * 2>>>(noise, ew2, eb2, out_trig, out_edge);
}

// round 10
// speedup vs baseline: 1.5017x; 1.0792x over previous
#include <cuda_runtime.h>
#include <cuda_fp16.h>
#include <cstdint>

#define N_NODES    2048
#define FDIM       256
#define HID        64
#define TEMPLATE_N 10
#define TRIG_ELEMS (N_NODES * FDIM)
#define EW1B_OFF   (FDIM * HID)

// device scratch (fp16 operand caches, produced by kP)
__device__ float   g_h3[FDIM];
__device__ __half2 g_baseh2[HID / 2];          // base = h3@(w1a+w1b)+eb1
__device__ __half2 g_npah2[N_NODES * HID / 2]; // 0.1*noise@w1a  (rows<10: 0)
__device__ __half2 g_npbh2[N_NODES * HID / 2]; // 0.1*noise@w1b  (rows<10: 0)

// ---- f32x2 helpers (prep GEMM only) --------------------------------------
__device__ __forceinline__ unsigned long long f2_fma(unsigned long long a, unsigned long long b, unsigned long long c) {
    unsigned long long r; asm("fma.rn.f32x2 %0, %1, %2, %3;" : "=l"(r) : "l"(a), "l"(b), "l"(c)); return r;
}
__device__ __forceinline__ void f2_unpack(float& lo, float& hi, unsigned long long v) {
    asm("mov.b64 {%0, %1}, %2;" : "=f"(lo), "=f"(hi) : "l"(v));
}
__device__ __forceinline__ unsigned long long f2_pack(float lo, float hi) {
    unsigned long long r; asm("mov.b64 %0, {%1, %2};" : "=l"(r) : "f"(lo), "f"(hi)); return r;
}

// ---------------------------------------------------------------------------
// Kernel P: 257 blocks x 256 threads. (unchanged from R9 — measured good)
//   block 0   : MLP -> g_h3, g_baseh2
//   blocks 1+ : noise GEMM, 8 rows/block -> g_npah2 / g_npbh2 (fp16)
// ---------------------------------------------------------------------------
#define KP_ROWS   8
#define NS_STRIDE 12   // 8 + pad; k*12 floats -> 16B aligned

__global__ void __launch_bounds__(256, 2)
kP_prep(const float* __restrict__ cf, const int* __restrict__ sel,
        const float* __restrict__ w1, const float* __restrict__ b1,
        const float* __restrict__ w2, const float* __restrict__ b2,
        const float* __restrict__ w3, const float* __restrict__ b3,
        const float* __restrict__ ew1, const float* __restrict__ eb1,
        const float* __restrict__ noise)
{
    __shared__ float sBuf[FDIM * NS_STRIDE];   // 12 KB
    const int tid = threadIdx.x;

    if (blockIdx.x == 0) {
        float* proto = sBuf;
        float* h1    = sBuf + 256;
        float* h2    = sBuf + 320;
        float* h3S   = sBuf + 384;
        float* part  = sBuf + 640;

        {
            float s = 0.f;
            #pragma unroll
            for (int r = 0; r < TEMPLATE_N; ++r)
                s += cf[(size_t)sel[r] * FDIM + tid];
            proto[tid] = s * (1.0f / TEMPLATE_N);
        }
        __syncthreads();

        {
            const int c = tid & 63, q = tid >> 6, k0 = q * 64;
            float acc = 0.f;
            #pragma unroll 16
            for (int k = 0; k < 64; ++k)
                acc = fmaf(proto[k0 + k], w1[(k0 + k) * HID + c], acc);
            part[tid] = acc;
        }
        __syncthreads();
        if (tid < HID)
            h1[tid] = fmaxf(part[tid] + part[64 + tid] + part[128 + tid] + part[192 + tid] + b1[tid], 0.f);
        __syncthreads();

        {
            const int c = tid & 63, q = tid >> 6, k0 = q * 16;
            float acc = 0.f;
            #pragma unroll
            for (int k = 0; k < 16; ++k)
                acc = fmaf(h1[k0 + k], w2[(k0 + k) * HID + c], acc);
            part[tid] = acc;
        }
        __syncthreads();
        if (tid < HID)
            h2[tid] = fmaxf(part[tid] + part[64 + tid] + part[128 + tid] + part[192 + tid] + b2[tid], 0.f);
        __syncthreads();

        {
            float acc = b3[tid];
            #pragma unroll 16
            for (int k = 0; k < HID; ++k)
                acc = fmaf(h2[k], w3[k * FDIM + tid], acc);
            float v = __fdividef(1.0f, 1.0f + __expf(-acc));
            g_h3[tid] = v;
            h3S[tid]  = v;
        }
        __syncthreads();

        {
            const int c = tid & 63, q = tid >> 6, k0 = q * 64;
            float acc = 0.f;
            #pragma unroll 8
            for (int k = 0; k < 64; ++k) {
                float w = ew1[(k0 + k) * HID + c] + ew1[EW1B_OFF + (k0 + k) * HID + c];
                acc = fmaf(h3S[k0 + k], w, acc);
            }
            part[tid] = acc;
        }
        __syncthreads();
        if (tid < HID) {
            float v = part[tid] + part[64 + tid] + part[128 + tid] + part[192 + tid] + eb1[tid];
            reinterpret_cast<__half*>(g_baseh2)[tid] = __float2half(v);
        }
        return;
    }

    // ---------------- noise GEMM (blocks 1..256), 8 rows each ----------------
    float* nS = sBuf;
    const int r0 = (blockIdx.x - 1) * KP_ROWS;

    #pragma unroll
    for (int u = 0; u < KP_ROWS; ++u) {
        const int r = r0 + u;
        float v = 0.f;
        if (r >= TEMPLATE_N)
            v = 0.1f * noise[(size_t)(r - TEMPLATE_N) * FDIM + tid];
        nS[tid * NS_STRIDE + u] = v;
    }
    __syncthreads();

    const int c  = tid & 127;
    const int rh = tid >> 7;
    const bool is_pa = (c < HID);
    const float* wcol = ew1 + (is_pa ? c : (EW1B_OFF + (c - HID)));

    unsigned long long acc0 = f2_pack(0.f, 0.f), acc1 = acc0;

    #pragma unroll 8
    for (int k = 0; k < FDIM; ++k) {
        const float w = wcol[k * HID];
        const unsigned long long wp = f2_pack(w, w);
        const ulonglong2 A = *reinterpret_cast<const ulonglong2*>(nS + k * NS_STRIDE + rh * 4);
        acc0 = f2_fma(A.x, wp, acc0);
        acc1 = f2_fma(A.y, wp, acc1);
    }

    __half* dst = reinterpret_cast<__half*>(is_pa ? g_npah2 : g_npbh2);
    const int cc = is_pa ? c : (c - HID);
    const int rb = r0 + rh * 4;
    float lo, hi;
    f2_unpack(lo, hi, acc0);
    dst[(rb + 0) * HID + cc] = __float2half(lo);
    dst[(rb + 1) * HID + cc] = __float2half(hi);
    f2_unpack(lo, hi, acc1);
    dst[(rb + 2) * HID + cc] = __float2half(lo);
    dst[(rb + 3) * HID + cc] = __float2half(hi);
}

// ---------------------------------------------------------------------------
// Kernel E: 544 tiles (128 j x 32 i), 256 threads, 4 CTAs/SM, ONE wave.
//   Lane pairs share a j: jl = warp*16 + lane/2, kh = lane&1 (32 k's each).
//   Partial dot combined with shfl_xor(1); even lane stores row i, odd
//   lane stores row i+1. No sum smem, no second sync, no epilogue pass.
// ---------------------------------------------------------------------------
#define TI 32
#define TJ 128
#define N_TILES 544     // sum over jt=0..15 of (4*jt + 4)

__global__ void __launch_bounds__(256, 4)
kE_edges(const float* __restrict__ noise,
         const float* __restrict__ ew2,
         const float* __restrict__ eb2,
         float* __restrict__ out_trig,
         float* __restrict__ out_edge)
{
    __shared__ __half2 paS[TI * 32];          // 4 KB   [ii][kp], kp = k/2
    __shared__ __half2 w2S[32];               // 128 B
    const int tid = threadIdx.x;

    // ---- stage 0: trig rows (<=4 per block) ----
    {
        const float h3v = g_h3[tid];
        for (int r = blockIdx.x; r < N_NODES; r += N_TILES) {
            float v = h3v;
            if (r >= TEMPLATE_N)
                v = fmaf(0.1f, noise[(size_t)(r - TEMPLATE_N) * FDIM + tid], v);
            out_trig[(size_t)r * FDIM + tid] = v;
        }
    }

    // ---- tile mapping: jt has 4*jt+4 i-tiles ----
    int rem = blockIdx.x, jt;
    for (jt = 0; jt < 16; ++jt) { const int n = 4 * jt + 4; if (rem < n) break; rem -= n; }
    const int it = rem;
    const int j0 = jt * TJ;
    const int i0 = it * TI;

    const int lane = tid & 31;
    const int warp = tid >> 5;
    const int jl = warp * 16 + (lane >> 1);   // 0..127
    const int kh = lane & 1;                  // k-half
    const int j  = j0 + jl;

    // ---- pa tile: half2 loads + half2 base add, 4 entries per thread ----
    #pragma unroll
    for (int idx = tid; idx < TI * 32; idx += 256) {
        const int ii = idx >> 5, kp = idx & 31;
        paS[idx] = __hadd2(g_npah2[(i0 + ii) * 32 + kp], g_baseh2[kp]);
    }
    if (tid < 16) {
        const float4 w = __ldg(reinterpret_cast<const float4*>(ew2) + tid);
        w2S[2 * tid]     = __floats2half2_rn(w.x, w.y);
        w2S[2 * tid + 1] = __floats2half2_rn(w.z, w.w);
    }

    // ---- pb: this thread's k-half of row j (4 x uint4 = 32 halves) ----
    uint4 pbr[4];
    {
        const uint4* pbp = reinterpret_cast<const uint4*>(g_npbh2 + j * 32 + kh * 16);
        #pragma unroll
        for (int q = 0; q < 4; ++q) pbr[q] = pbp[q];
    }
    __syncthreads();

    // ---- w2 k-half into regs ----
    uint4 w2r[4];
    {
        const uint4* wp = reinterpret_cast<const uint4*>(w2S) + kh * 4;
        #pragma unroll
        for (int q = 0; q < 4; ++q) w2r[q] = wp[q];
    }

    const float ebb = eb2[0];
    const __half2 one2 = __half2half2(__ushort_as_half(0x3C00));

    // ---- pair loop: 2 i's per iteration, 8 acc chains, shuffle combine ----
    const uint4* paS4 = reinterpret_cast<const uint4*>(paS);   // 8 uint4 per i-row
    #pragma unroll 4
    for (int ii = 0; ii < TI; ii += 2) {
        __half2 a0 = __float2half2_rn(0.f), a1 = a0, a2 = a0, a3 = a0;
        __half2 b0 = a0, b1 = a0, b2 = a0, b3 = a0;

        const uint4* pa0 = paS4 + ii * 8 + kh * 4;
        const uint4* pa1 = pa0 + 8;

        #pragma unroll
        for (int q = 0; q < 4; ++q) {
            const uint4 PA = pa0[q];               // 2 distinct LDS lines/warp
            const uint4 PB = pa1[q];
            const uint4 W  = w2r[q];
            const __half2 w0  = *reinterpret_cast<const __half2*>(&W.x);
            const __half2 w1v = *reinterpret_cast<const __half2*>(&W.y);
            const __half2 w2v = *reinterpret_cast<const __half2*>(&W.z);
            const __half2 w3v = *reinterpret_cast<const __half2*>(&W.w);
            const uint4 B = pbr[q];
            const __half2 q0 = *reinterpret_cast<const __half2*>(&B.x);
            const __half2 q1 = *reinterpret_cast<const __half2*>(&B.y);
            const __half2 q2 = *reinterpret_cast<const __half2*>(&B.z);
            const __half2 q3 = *reinterpret_cast<const __half2*>(&B.w);
            __half2 h;
            h = __hfma2_relu(*reinterpret_cast<const __half2*>(&PA.x), one2, q0); a0 = __hfma2(h, w0, a0);
            h = __hfma2_relu(*reinterpret_cast<const __half2*>(&PA.y), one2, q1); a1 = __hfma2(h, w1v, a1);
            h = __hfma2_relu(*reinterpret_cast<const __half2*>(&PA.z), one2, q2); a2 = __hfma2(h, w2v, a2);
            h = __hfma2_relu(*reinterpret_cast<const __half2*>(&PA.w), one2, q3); a3 = __hfma2(h, w3v, a3);
            h = __hfma2_relu(*reinterpret_cast<const __half2*>(&PB.x), one2, q0); b0 = __hfma2(h, w0, b0);
            h = __hfma2_relu(*reinterpret_cast<const __half2*>(&PB.y), one2, q1); b1 = __hfma2(h, w1v, b1);
            h = __hfma2_relu(*reinterpret_cast<const __half2*>(&PB.z), one2, q2); b2 = __hfma2(h, w2v, b2);
            h = __hfma2_relu(*reinterpret_cast<const __half2*>(&PB.w), one2, q3); b3 = __hfma2(h, w3v, b3);
        }

        // combine halves within the lane pair
        const __half2 ta = __hadd2(__hadd2(a0, a1), __hadd2(a2, a3));
        const __half2 tb = __hadd2(__hadd2(b0, b1), __hadd2(b2, b3));
        const float2 fa = __half22float2(ta);
        const float2 fb = __half22float2(tb);
        float sA = fa.x + fa.y;
        float sB = fb.x + fb.y;
        sA += __shfl_xor_sync(0xFFFFFFFFu, sA, 1);
        sB += __shfl_xor_sync(0xFFFFFFFFu, sB, 1);

        // even lane stores row i (sA), odd lane stores row i+1 (sB)
        const int i = i0 + ii + kh;
        const float s = (kh ? sB : sA) + ebb;
        if (j > i) {
            const float pr = __fdividef(1.0f, 1.0f + __expf(-s));
            const int base = i * (2 * N_NODES - i - 1) / 2;
            out_edge[base + (j - i - 1)] = pr;
        }
    }
}

// ---------------------------------------------------------------------------
extern "C" void kernel_launch(void* const* d_in, const int* in_sizes, int n_in,
                              void* d_out, int out_size)
{
    const float* cf    = (const float*)d_in[0];
    const int*   sel   = (const int*)  d_in[1];
    const float* noise = (const float*)d_in[2];
    const float* g1w   = (const float*)d_in[3];
    const float* g1b   = (const float*)d_in[4];
    const float* g2w   = (const float*)d_in[5];
    const float* g2b   = (const float*)d_in[6];
    const float* g3w   = (const float*)d_in[7];
    const float* g3b   = (const float*)d_in[8];
    const float* ew1   = (const float*)d_in[9];
    const float* eb1   = (const float*)d_in[10];
    const float* ew2   = (const float*)d_in[11];
    const float* eb2   = (const float*)d_in[12];

    float* out      = (float*)d_out;
    float* out_trig = out;
    float* out_edge = out + TRIG_ELEMS;

    kP_prep<<<257, 256>>>(cf, sel, g1w, g1b, g2w, g2b, g3w, g3b, ew1, eb1, noise);
    kE_edges<<<N_TILES, 256>>>(noise, ew2, eb2, out_trig, out_edge);
}